// round 1
// baseline (speedup 1.0000x reference)
#include <cuda_runtime.h>
#include <cstddef>

// KPN per-pixel dynamic convolution, K=15
// data:    [1, 8, 3, 96, 96]      float32
// kernels: [1, 8, 225, 3, 96, 96] float32   (tap-major: k = i*15 + j)
// out:     [1, 8, 3, 96, 96]      float32

#define KSZ    15
#define PAD    7
#define HH     96
#define WW     96
#define CCH    3
#define TTT    8
#define TILE_H 8
#define SMEM_W 112                 // 96 + 14 halo = 110, padded to 112 (16B align)
#define SMEM_H (TILE_H + KSZ - 1)  // 22
#define SLAB   (HH * WW)           // 9216
#define KSTRIDE (CCH * HH * WW)    // 27648 floats between consecutive taps

__global__ __launch_bounds__(192)
void kpn_kernel(const float* __restrict__ data,
                const float* __restrict__ kernels,
                float* __restrict__ out)
{
    __shared__ float tile[SMEM_H * SMEM_W];

    const int tc = blockIdx.y;             // t*3 + c, 0..23
    const int h0 = blockIdx.x * TILE_H;    // output row base
    const float* dslab = data + (size_t)tc * SLAB;

    // ---- cooperative load of padded data tile (zero-pad OOB) ----
    const int tid = threadIdx.y * 24 + threadIdx.x;   // 0..191
    for (int idx = tid; idx < SMEM_H * SMEM_W; idx += 192) {
        const int r  = idx / SMEM_W;
        const int cc = idx - r * SMEM_W;
        const int gh = h0 - PAD + r;
        const int gw = cc - PAD;
        float v = 0.0f;
        if ((unsigned)gh < (unsigned)HH && (unsigned)gw < (unsigned)WW)
            v = dslab[gh * WW + gw];
        tile[idx] = v;
    }
    __syncthreads();

    // ---- each thread produces 4 consecutive w pixels ----
    const int w = threadIdx.x * 4;         // 0,4,...,92
    const int h = h0 + threadIdx.y;
    const int t = tc / CCH;
    const int c = tc - t * CCH;

    // kernels[t, k, c, h, w] with k varying: base + k*KSTRIDE
    const float* kbase = kernels
        + ((size_t)(t * (KSZ * KSZ)) * CCH + c) * SLAB
        + (size_t)h * WW + w;

    float acc0 = 0.0f, acc1 = 0.0f, acc2 = 0.0f, acc3 = 0.0f;

    #pragma unroll 3
    for (int i = 0; i < KSZ; i++) {
        // data row segment: smem cols w .. w+19 (covers taps j=0..14 for 4 outputs)
        const float* row = &tile[(threadIdx.y + i) * SMEM_W + w];
        float d[20];
        #pragma unroll
        for (int v4 = 0; v4 < 5; v4++) {
            const float4 rv = *reinterpret_cast<const float4*>(row + v4 * 4);
            d[v4 * 4 + 0] = rv.x;
            d[v4 * 4 + 1] = rv.y;
            d[v4 * 4 + 2] = rv.z;
            d[v4 * 4 + 3] = rv.w;
        }
        const float* kp = kbase + (size_t)(i * KSZ) * KSTRIDE;
        #pragma unroll
        for (int j = 0; j < KSZ; j++) {
            const float4 kv = *reinterpret_cast<const float4*>(kp + (size_t)j * KSTRIDE);
            acc0 = fmaf(kv.x, d[j + 0], acc0);
            acc1 = fmaf(kv.y, d[j + 1], acc1);
            acc2 = fmaf(kv.z, d[j + 2], acc2);
            acc3 = fmaf(kv.w, d[j + 3], acc3);
        }
    }

    *reinterpret_cast<float4*>(out + (size_t)tc * SLAB + (size_t)h * WW + w)
        = make_float4(acc0, acc1, acc2, acc3);
}

extern "C" void kernel_launch(void* const* d_in, const int* in_sizes, int n_in,
                              void* d_out, int out_size)
{
    // data is the small tensor (221184), kernels the big one (49766400);
    // detect by size to be robust to metadata ordering.
    const float* data;
    const float* kernels;
    if (in_sizes[0] < in_sizes[1]) {
        data    = (const float*)d_in[0];
        kernels = (const float*)d_in[1];
    } else {
        data    = (const float*)d_in[1];
        kernels = (const float*)d_in[0];
    }

    dim3 grid(HH / TILE_H, TTT * CCH);   // (12, 24) = 288 blocks
    dim3 block(WW / 4, TILE_H);          // (24, 8)  = 192 threads
    kpn_kernel<<<grid, block>>>(data, kernels, (float*)d_out);
}

// round 2
// speedup vs baseline: 1.4406x; 1.4406x over previous
#include <cuda_runtime.h>
#include <cstddef>

// KPN per-pixel dynamic convolution, K=15, tap-split (split-K over kernel rows)
// data:    [1, 8, 3, 96, 96]      float32
// kernels: [1, 8, 225, 3, 96, 96] float32   (tap-major: k = i*15 + j)
// out:     [1, 8, 3, 96, 96]      float32

#define KSZ    15
#define PAD    7
#define HH     96
#define WW     96
#define CCH    3
#define TTT    8
#define TILE_H 8
#define ZSPLIT 3                   // 15 tap rows split 5/5/5 across threadIdx.z
#define ROWS_PER_Z (KSZ / ZSPLIT)  // 5
#define SMEM_W 112                 // 96 + 14 halo = 110, padded to 112 (16B align)
#define SMEM_H (TILE_H + KSZ - 1)  // 22
#define SLAB   (HH * WW)           // 9216
#define KSTRIDE (CCH * HH * WW)    // 27648 floats between consecutive taps
#define NTHREADS (24 * TILE_H * ZSPLIT)  // 576

__global__ __launch_bounds__(NTHREADS)
void kpn_kernel(const float* __restrict__ data,
                const float* __restrict__ kernels,
                float* __restrict__ out)
{
    __shared__ float tile[SMEM_H * SMEM_W];                       // 9856 B
    __shared__ float part[ZSPLIT - 1][TILE_H][24][4];             // 6144 B

    const int tc = blockIdx.y;             // t*3 + c, 0..23
    const int h0 = blockIdx.x * TILE_H;    // output row base
    const float* dslab = data + (size_t)tc * SLAB;

    const int tx = threadIdx.x;            // 0..23  (w / 4)
    const int ty = threadIdx.y;            // 0..7   (row in tile)
    const int tz = threadIdx.z;            // 0..2   (tap-row group)

    // ---- cooperative load of padded data tile (zero-pad OOB) ----
    const int tid = (tz * TILE_H + ty) * 24 + tx;   // 0..575
    for (int idx = tid; idx < SMEM_H * SMEM_W; idx += NTHREADS) {
        const int r  = idx / SMEM_W;
        const int cc = idx - r * SMEM_W;
        const int gh = h0 - PAD + r;
        const int gw = cc - PAD;
        float v = 0.0f;
        if ((unsigned)gh < (unsigned)HH && (unsigned)gw < (unsigned)WW)
            v = dslab[gh * WW + gw];
        tile[idx] = v;
    }
    __syncthreads();

    // ---- each (x,y) thread-triple produces 4 consecutive w pixels ----
    const int w = tx * 4;                  // 0,4,...,92
    const int h = h0 + ty;
    const int t = tc / CCH;
    const int c = tc - t * CCH;

    // kernels[t, k, c, h, w] with k varying: base + k*KSTRIDE
    const float* kbase = kernels
        + ((size_t)(t * (KSZ * KSZ)) * CCH + c) * SLAB
        + (size_t)h * WW + w;

    float acc0 = 0.0f, acc1 = 0.0f, acc2 = 0.0f, acc3 = 0.0f;

    #pragma unroll
    for (int ii = 0; ii < ROWS_PER_Z; ii++) {
        const int i = tz * ROWS_PER_Z + ii;      // global tap row 0..14
        // data row segment: smem cols w .. w+19 (taps j=0..14 for 4 outputs)
        const float* row = &tile[(ty + i) * SMEM_W + w];
        float d[20];
        #pragma unroll
        for (int v4 = 0; v4 < 5; v4++) {
            const float4 rv = *reinterpret_cast<const float4*>(row + v4 * 4);
            d[v4 * 4 + 0] = rv.x;
            d[v4 * 4 + 1] = rv.y;
            d[v4 * 4 + 2] = rv.z;
            d[v4 * 4 + 3] = rv.w;
        }
        const float* kp = kbase + (size_t)(i * KSZ) * KSTRIDE;

        // 15 taps in 3 batches of 5 float4 loads -> MLP ~5 per warp
        #pragma unroll
        for (int b = 0; b < 3; b++) {
            float4 kv[5];
            #pragma unroll
            for (int u = 0; u < 5; u++)
                kv[u] = *reinterpret_cast<const float4*>(
                    kp + (size_t)(b * 5 + u) * KSTRIDE);
            #pragma unroll
            for (int u = 0; u < 5; u++) {
                const int j = b * 5 + u;
                acc0 = fmaf(kv[u].x, d[j + 0], acc0);
                acc1 = fmaf(kv[u].y, d[j + 1], acc1);
                acc2 = fmaf(kv[u].z, d[j + 2], acc2);
                acc3 = fmaf(kv[u].w, d[j + 3], acc3);
            }
        }
    }

    // ---- cross-z reduction through shared memory ----
    if (tz > 0) {
        part[tz - 1][ty][tx][0] = acc0;
        part[tz - 1][ty][tx][1] = acc1;
        part[tz - 1][ty][tx][2] = acc2;
        part[tz - 1][ty][tx][3] = acc3;
    }
    __syncthreads();
    if (tz == 0) {
        acc0 += part[0][ty][tx][0] + part[1][ty][tx][0];
        acc1 += part[0][ty][tx][1] + part[1][ty][tx][1];
        acc2 += part[0][ty][tx][2] + part[1][ty][tx][2];
        acc3 += part[0][ty][tx][3] + part[1][ty][tx][3];
        *reinterpret_cast<float4*>(out + (size_t)tc * SLAB + (size_t)h * WW + w)
            = make_float4(acc0, acc1, acc2, acc3);
    }
}

extern "C" void kernel_launch(void* const* d_in, const int* in_sizes, int n_in,
                              void* d_out, int out_size)
{
    // data is the small tensor (221184), kernels the big one (49766400);
    // detect by size to be robust to metadata ordering.
    const float* data;
    const float* kernels;
    if (in_sizes[0] < in_sizes[1]) {
        data    = (const float*)d_in[0];
        kernels = (const float*)d_in[1];
    } else {
        data    = (const float*)d_in[1];
        kernels = (const float*)d_in[0];
    }

    dim3 grid(HH / TILE_H, TTT * CCH);      // (12, 24) = 288 blocks
    dim3 block(WW / 4, TILE_H, ZSPLIT);     // (24, 8, 3) = 576 threads
    kpn_kernel<<<grid, block>>>(data, kernels, (float*)d_out);
}